// round 2
// baseline (speedup 1.0000x reference)
#include <cuda_runtime.h>
#include <cuda_bf16.h>

// CovarianceResidualError:
//   a_i        = graph_emb[i, 0]
//   ACC_j      = sum_i errors[i,j] * a_i
//   SE_j       = sum_i errors[i,j]
//   SA         = sum_i a_i
//   col_sums_j = ACC_j - SA*SE_j/N        (mean-centering identity)
//   out        = -sum_j |col_sums_j|
//
// K1: 512 blocks x 256 threads -> per-block partials (deterministic).
// K2: 256 blocks (one per column) reduce partials; last-arriving block
//     does the deterministic fixed-order final sum of the 256 |col_sums|.

#define NROWS 131072
#define OCOLS 256
#define DCOLS 128
#define NB 512
#define ROWS_PER_BLK (NROWS / NB)          // 256

__device__ float g_pacc[NB * OCOLS];
__device__ float g_pse [NB * OCOLS];
__device__ float g_psa [NB];
__device__ float g_colv[OCOLS];
__device__ unsigned int g_count = 0;

__global__ void __launch_bounds__(256, 4)
cov_partial_kernel(const float* __restrict__ ge, const float4* __restrict__ err4)
{
    __shared__ float a_sh[ROWS_PER_BLK];
    __shared__ float red[4 * OCOLS];

    const int tid  = threadIdx.x;
    const int tx   = tid & 63;     // column group: columns 4*tx .. 4*tx+3
    const int ty   = tid >> 6;     // row phase 0..3
    const int row0 = blockIdx.x * ROWS_PER_BLK;

    // One strided a-column load per thread (row tid of this block's 256 rows)
    const float a_mine = ge[(size_t)(row0 + tid) * DCOLS];
    a_sh[tid] = a_mine;
    __syncthreads();

    float4 acc = make_float4(0.f, 0.f, 0.f, 0.f);
    float4 se  = make_float4(0.f, 0.f, 0.f, 0.f);

    #pragma unroll 8
    for (int r = ty; r < ROWS_PER_BLK; r += 4) {
        const float4 e = err4[(size_t)(row0 + r) * (OCOLS / 4) + tx];
        const float  a = a_sh[r];
        acc.x = fmaf(e.x, a, acc.x); acc.y = fmaf(e.y, a, acc.y);
        acc.z = fmaf(e.z, a, acc.z); acc.w = fmaf(e.w, a, acc.w);
        se.x += e.x; se.y += e.y; se.z += e.z; se.w += e.w;
    }

    // Reduce across the 4 row phases (deterministic, via shared)
    __syncthreads();
    red[ty * OCOLS + 4 * tx + 0] = acc.x;
    red[ty * OCOLS + 4 * tx + 1] = acc.y;
    red[ty * OCOLS + 4 * tx + 2] = acc.z;
    red[ty * OCOLS + 4 * tx + 3] = acc.w;
    __syncthreads();
    g_pacc[blockIdx.x * OCOLS + tid] =
        red[tid] + red[OCOLS + tid] + red[2 * OCOLS + tid] + red[3 * OCOLS + tid];
    __syncthreads();
    red[ty * OCOLS + 4 * tx + 0] = se.x;
    red[ty * OCOLS + 4 * tx + 1] = se.y;
    red[ty * OCOLS + 4 * tx + 2] = se.z;
    red[ty * OCOLS + 4 * tx + 3] = se.w;
    __syncthreads();
    g_pse[blockIdx.x * OCOLS + tid] =
        red[tid] + red[OCOLS + tid] + red[2 * OCOLS + tid] + red[3 * OCOLS + tid];

    // Block partial of SA: fixed-shape tree over the 256 a values
    __syncthreads();
    red[tid] = a_mine;
    __syncthreads();
    #pragma unroll
    for (int s = 128; s > 0; s >>= 1) {
        if (tid < s) red[tid] += red[tid + s];
        __syncthreads();
    }
    if (tid == 0) g_psa[blockIdx.x] = red[0];
}

__global__ void __launch_bounds__(256, 4)
cov_reduce_kernel(float* __restrict__ out)
{
    __shared__ float sh[256];
    __shared__ unsigned int s_ticket;

    const int tid = threadIdx.x;
    const int c   = blockIdx.x;    // this block's column

    // ---- SA (every block computes it redundantly; tiny, L2-hit) ----
    sh[tid] = g_psa[tid] + g_psa[tid + 256];
    __syncthreads();
    #pragma unroll
    for (int s = 128; s > 0; s >>= 1) {
        if (tid < s) sh[tid] += sh[tid + s];
        __syncthreads();
    }
    const float SA = sh[0];
    __syncthreads();

    // ---- column reductions over 512 block partials ----
    const float a2 = g_pacc[(size_t)tid * OCOLS + c] +
                     g_pacc[(size_t)(tid + 256) * OCOLS + c];
    const float s2 = g_pse [(size_t)tid * OCOLS + c] +
                     g_pse [(size_t)(tid + 256) * OCOLS + c];

    sh[tid] = a2;
    __syncthreads();
    #pragma unroll
    for (int s = 128; s > 0; s >>= 1) {
        if (tid < s) sh[tid] += sh[tid + s];
        __syncthreads();
    }
    const float A_c = sh[0];
    __syncthreads();
    sh[tid] = s2;
    __syncthreads();
    #pragma unroll
    for (int s = 128; s > 0; s >>= 1) {
        if (tid < s) sh[tid] += sh[tid + s];
        __syncthreads();
    }
    const float S_c = sh[0];

    if (tid == 0) {
        const float k = SA * (1.0f / (float)NROWS);
        g_colv[c] = fabsf(A_c - k * S_c);
        __threadfence();
        s_ticket = atomicAdd(&g_count, 1u);
    }
    __syncthreads();

    // ---- last-arriving block does the deterministic final sum ----
    if (s_ticket == OCOLS - 1) {
        __threadfence();
        sh[tid] = g_colv[tid];
        __syncthreads();
        #pragma unroll
        for (int s = 128; s > 0; s >>= 1) {
            if (tid < s) sh[tid] += sh[tid + s];
            __syncthreads();
        }
        if (tid == 0) {
            out[0] = -sh[0];
            g_count = 0;          // reset for next graph replay
            __threadfence();
        }
    }
}

extern "C" void kernel_launch(void* const* d_in, const int* in_sizes, int n_in,
                              void* d_out, int out_size)
{
    const float* ge  = nullptr;   // graph_emb (N x 128)
    const float* err = nullptr;   // errors    (N x 256)
    for (int i = 0; i < n_in; ++i) {
        if (in_sizes[i] == NROWS * DCOLS) ge  = (const float*)d_in[i];
        else if (in_sizes[i] == NROWS * OCOLS) err = (const float*)d_in[i];
    }

    cov_partial_kernel<<<NB, 256>>>(ge, (const float4*)err);
    cov_reduce_kernel<<<OCOLS, 256>>>((float*)d_out);
}

// round 3
// speedup vs baseline: 1.0692x; 1.0692x over previous
#include <cuda_runtime.h>
#include <cuda_bf16.h>

// CovarianceResidualError:
//   a_i = graph_emb[i,0];  ACC_j = sum_i e_ij*a_i;  SE_j = sum_i e_ij;  SA = sum_i a_i
//   out = -sum_j |ACC_j - SA*SE_j/N|
//
// K1: 512 blocks x 256 threads -> per-block partials (R1 proven version).
// K2: 32 blocks x 256 threads, coalesced column reduce; last-arriving block
//     (ticket) does SA + the deterministic final |.| sum.

#define NROWS 131072
#define OCOLS 256
#define DCOLS 128
#define NB 512
#define ROWS_PER_BLK (NROWS / NB)          // 256
#define CHUNK 64
#define NCHUNK (ROWS_PER_BLK / CHUNK)      // 4

__device__ float g_pacc[NB * OCOLS];
__device__ float g_pse [NB * OCOLS];
__device__ float g_psa [NB];
__device__ float g_colA[OCOLS];
__device__ float g_colS[OCOLS];
__device__ unsigned int g_count = 0;

__global__ void __launch_bounds__(256, 4)
cov_partial_kernel(const float* __restrict__ ge, const float4* __restrict__ err4)
{
    __shared__ float a_sh[CHUNK];
    __shared__ float red[4 * OCOLS];

    const int tid  = threadIdx.x;
    const int tx   = tid & 63;     // column group: columns 4*tx .. 4*tx+3
    const int ty   = tid >> 6;     // row phase 0..3
    const int row0 = blockIdx.x * ROWS_PER_BLK;

    float4 acc = make_float4(0.f, 0.f, 0.f, 0.f);
    float4 se  = make_float4(0.f, 0.f, 0.f, 0.f);
    float  suma = 0.f;

    float a_next = 0.f;
    if (tid < CHUNK)
        a_next = ge[(size_t)(row0 + tid) * DCOLS];

    for (int c = 0; c < NCHUNK; ++c) {
        const int base = row0 + c * CHUNK;
        __syncthreads();
        if (tid < CHUNK) { a_sh[tid] = a_next; suma += a_next; }
        __syncthreads();
        if (tid < CHUNK && (c + 1) < NCHUNK)
            a_next = ge[(size_t)(base + CHUNK + tid) * DCOLS];

        #pragma unroll
        for (int r = ty; r < CHUNK; r += 4) {
            const float4 e = err4[(size_t)(base + r) * (OCOLS / 4) + tx];
            const float  a = a_sh[r];
            acc.x = fmaf(e.x, a, acc.x); acc.y = fmaf(e.y, a, acc.y);
            acc.z = fmaf(e.z, a, acc.z); acc.w = fmaf(e.w, a, acc.w);
            se.x += e.x; se.y += e.y; se.z += e.z; se.w += e.w;
        }
    }

    __syncthreads();
    red[ty * OCOLS + 4 * tx + 0] = acc.x;
    red[ty * OCOLS + 4 * tx + 1] = acc.y;
    red[ty * OCOLS + 4 * tx + 2] = acc.z;
    red[ty * OCOLS + 4 * tx + 3] = acc.w;
    __syncthreads();
    g_pacc[blockIdx.x * OCOLS + tid] =
        red[tid] + red[OCOLS + tid] + red[2 * OCOLS + tid] + red[3 * OCOLS + tid];
    __syncthreads();
    red[ty * OCOLS + 4 * tx + 0] = se.x;
    red[ty * OCOLS + 4 * tx + 1] = se.y;
    red[ty * OCOLS + 4 * tx + 2] = se.z;
    red[ty * OCOLS + 4 * tx + 3] = se.w;
    __syncthreads();
    g_pse[blockIdx.x * OCOLS + tid] =
        red[tid] + red[OCOLS + tid] + red[2 * OCOLS + tid] + red[3 * OCOLS + tid];

    __syncthreads();
    if (tid < CHUNK) red[tid] = suma;
    __syncthreads();
    if (tid == 0) {
        float s = 0.f;
        #pragma unroll
        for (int i = 0; i < CHUNK; ++i) s += red[i];
        g_psa[blockIdx.x] = s;
    }
}

__global__ void __launch_bounds__(256, 4)
cov_colreduce_kernel(float* __restrict__ out)
{
    __shared__ float shA[32][8];
    __shared__ float shS[32][8];
    __shared__ float shr[256];
    __shared__ unsigned int s_ticket;

    const int tid = threadIdx.x;
    const int cc  = tid & 7;       // column within this block's group of 8
    const int r   = tid >> 3;      // 0..31 partial-row lane
    const int c   = blockIdx.x * 8 + cc;

    // Coalesced column reduce: warp reads 4 rows x 8 consecutive floats
    // (four fully-utilized 32B sectors per load instruction).
    float a = 0.f, s = 0.f;
    #pragma unroll
    for (int k = 0; k < NB / 32; ++k) {        // 16 steps
        const int row = r + k * 32;
        a += g_pacc[(size_t)row * OCOLS + c];
        s += g_pse [(size_t)row * OCOLS + c];
    }
    shA[r][cc] = a;
    shS[r][cc] = s;
    __syncthreads();
    #pragma unroll
    for (int st = 16; st > 0; st >>= 1) {
        if (r < st) {
            shA[r][cc] += shA[r + st][cc];
            shS[r][cc] += shS[r + st][cc];
        }
        __syncthreads();
    }
    if (r == 0) {
        g_colA[c] = shA[0][cc];
        g_colS[c] = shS[0][cc];
    }

    if (tid == 0) {
        __threadfence();
        s_ticket = atomicAdd(&g_count, 1u);
    }
    __syncthreads();

    // ---- last-arriving block: SA + deterministic final sum ----
    if (s_ticket == gridDim.x - 1) {
        __threadfence();
        // SA over 512 block partials (fixed-shape tree)
        shr[tid] = g_psa[tid] + g_psa[tid + 256];
        __syncthreads();
        #pragma unroll
        for (int st = 128; st > 0; st >>= 1) {
            if (tid < st) shr[tid] += shr[tid + st];
            __syncthreads();
        }
        const float k = shr[0] * (1.0f / (float)NROWS);
        __syncthreads();

        shr[tid] = fabsf(g_colA[tid] - k * g_colS[tid]);
        __syncthreads();
        #pragma unroll
        for (int st = 128; st > 0; st >>= 1) {
            if (tid < st) shr[tid] += shr[tid + st];
            __syncthreads();
        }
        if (tid == 0) {
            out[0] = -shr[0];
            g_count = 0;           // reset for next graph replay
            __threadfence();
        }
    }
}

extern "C" void kernel_launch(void* const* d_in, const int* in_sizes, int n_in,
                              void* d_out, int out_size)
{
    const float* ge  = nullptr;   // graph_emb (N x 128)
    const float* err = nullptr;   // errors    (N x 256)
    for (int i = 0; i < n_in; ++i) {
        if (in_sizes[i] == NROWS * DCOLS) ge  = (const float*)d_in[i];
        else if (in_sizes[i] == NROWS * OCOLS) err = (const float*)d_in[i];
    }

    cov_partial_kernel<<<NB, 256>>>(ge, (const float4*)err);
    cov_colreduce_kernel<<<32, 256>>>((float*)d_out);
}